// round 4
// baseline (speedup 1.0000x reference)
#include <cuda_runtime.h>
#include <cuda_fp16.h>
#include <math.h>

#define NV_MAX   1048576
#define MAX_SEG  50000
#define D        12
#define ROW_PAD  16          // halves per padded row = 32 bytes = 1 L2 sector
#define EPS      1e-12f
#define CHUNK    4096        // token staging tile (vox+seg = 32KB smem)
#define VPB      256         // voxels per block

// Token-range partition per pool block: g_part[b] = lower_bound(vox, b*VPB).
__device__ int g_part[NV_MAX / VPB + 1];
// fp16 table repacked to 32B-aligned rows (one L2 sector per gather).
__device__ __align__(32) __half g_tab[MAX_SEG * ROW_PAD];

// One thread per table row: read 12 floats, write 16 halves (32B).
__global__ __launch_bounds__(256) void k_repack(const float* __restrict__ table, int rows) {
    int r = blockIdx.x * blockDim.x + threadIdx.x;
    if (r >= rows) return;
    const float4* src = (const float4*)(table + (size_t)r * D);
    float4 a = __ldg(src + 0);
    float4 b = __ldg(src + 1);
    float4 c = __ldg(src + 2);
    __half2 h[8];
    h[0] = __floats2half2_rn(a.x, a.y);
    h[1] = __floats2half2_rn(a.z, a.w);
    h[2] = __floats2half2_rn(b.x, b.y);
    h[3] = __floats2half2_rn(b.z, b.w);
    h[4] = __floats2half2_rn(c.x, c.y);
    h[5] = __floats2half2_rn(c.z, c.w);
    h[6] = __floats2half2_rn(0.f, 0.f);
    h[7] = __floats2half2_rn(0.f, 0.f);
    uint4* dst = (uint4*)(g_tab + (size_t)r * ROW_PAD);
    dst[0] = *(uint4*)&h[0];
    dst[1] = *(uint4*)&h[4];
}

// One thread per pool block (plus one sentinel): binary search token partition.
__global__ __launch_bounds__(256) void k_part(const int* __restrict__ vox,
                                              int T, int nparts) {
    int b = blockIdx.x * blockDim.x + threadIdx.x;
    if (b > nparts) return;
    int key = b * VPB;     // first voxel of block b
    int lo = 0, hi = T;
    while (lo < hi) {
        int m = (lo + hi) >> 1;
        if (__ldg(vox + m) < key) lo = m + 1; else hi = m;
    }
    g_part[b] = lo;
}

__device__ __forceinline__ int lbound_smem(const int* a, int n, int key) {
    int lo = 0, hi = n;
    while (lo < hi) {
        int m = (lo + hi) >> 1;
        if (a[m] < key) lo = m + 1; else hi = m;
    }
    return lo;
}

__global__ __launch_bounds__(256) void k_pool(const int* __restrict__ seg,
                                              const int* __restrict__ vox,
                                              float*     __restrict__ out,
                                              int n_voxels) {
    __shared__ int s_vox[CHUNK];
    __shared__ int s_seg[CHUNK];

    int b = blockIdx.x;
    int v = b * VPB + threadIdx.x;

    int rs = g_part[b];
    int re = g_part[b + 1];

    float acc[D];
#pragma unroll
    for (int d = 0; d < D; d++) acc[d] = 0.0f;
    int cnt = 0;

    for (int cbase = rs; cbase < re; cbase += CHUNK) {
        int len = min(CHUNK, re - cbase);
        __syncthreads();
        for (int j = threadIdx.x; j < len; j += 256) {
            s_vox[j] = __ldg(vox + cbase + j);
            s_seg[j] = __ldg(seg + cbase + j);
        }
        __syncthreads();

        int lo = lbound_smem(s_vox, len, v);
        int hi = lbound_smem(s_vox, len, v + 1);
        cnt += hi - lo;

        for (int t = lo; t < hi; t++) {
            int sg = s_seg[t];
            const uint4* row = (const uint4*)(g_tab + (size_t)sg * ROW_PAD);
            uint4 p0 = __ldg(row + 0);
            uint4 p1 = __ldg(row + 1);
            float2 f;
            f = __half22float2(*(const __half2*)&p0.x); acc[0]  += f.x; acc[1]  += f.y;
            f = __half22float2(*(const __half2*)&p0.y); acc[2]  += f.x; acc[3]  += f.y;
            f = __half22float2(*(const __half2*)&p0.z); acc[4]  += f.x; acc[5]  += f.y;
            f = __half22float2(*(const __half2*)&p0.w); acc[6]  += f.x; acc[7]  += f.y;
            f = __half22float2(*(const __half2*)&p1.x); acc[8]  += f.x; acc[9]  += f.y;
            f = __half22float2(*(const __half2*)&p1.y); acc[10] += f.x; acc[11] += f.y;
        }
    }

    if (v >= n_voxels) return;

    float invc = 1.0f / (float)(cnt > 0 ? cnt : 1);

    float m[D];
    float norm2 = 0.0f;
#pragma unroll
    for (int d = 0; d < D; d++) {
        m[d] = acc[d] * invc;
        norm2 += m[d] * m[d];
    }
    float norm = sqrtf(norm2);
    float inv  = 1.0f / fmaxf(norm, EPS);

    float4 o0 = make_float4(m[0] * inv, m[1] * inv, m[2]  * inv, m[3]  * inv);
    float4 o1 = make_float4(m[4] * inv, m[5] * inv, m[6]  * inv, m[7]  * inv);
    float4 o2 = make_float4(m[8] * inv, m[9] * inv, m[10] * inv, m[11] * inv);

    float4* orow = (float4*)(out + (size_t)v * D);
    orow[0] = o0;
    orow[1] = o1;
    orow[2] = o2;
}

extern "C" void kernel_launch(void* const* d_in, const int* in_sizes, int n_in,
                              void* d_out, int out_size) {
    const float* table = (const float*)d_in[0];
    const int*   seg   = (const int*)  d_in[1];
    const int*   vox   = (const int*)  d_in[2];
    float*       out   = (float*)      d_out;

    int rows     = in_sizes[0] / D;
    int T        = in_sizes[1];
    int n_voxels = out_size / D;
    int nparts   = (n_voxels + VPB - 1) / VPB;

    k_repack<<<(rows + 255) / 256, 256>>>(table, rows);
    k_part<<<(nparts + 1 + 255) / 256, 256>>>(vox, T, nparts);
    k_pool<<<nparts, 256>>>(seg, vox, out, n_voxels);
}

// round 5
// speedup vs baseline: 1.1659x; 1.1659x over previous
#include <cuda_runtime.h>
#include <cuda_fp16.h>
#include <math.h>

#define NV_MAX   1048576
#define MAX_SEG  50000
#define D        12
#define ROW_PAD  16          // halves per padded row = 32 bytes = 1 L2 sector
#define EPS      1e-12f
#define CHUNK    2048        // seg-id staging tile (8KB smem)

// Per-voxel token range (monotone via gap-fill for empty voxels).
__device__ int g_start[NV_MAX];
__device__ int g_end[NV_MAX];
// fp16 table repacked to 32B-aligned rows (one L2 sector per gather).
__device__ __align__(32) __half g_tab[MAX_SEG * ROW_PAD];

// Fused prep: blocks [0, bblocks) do boundary detection (4 tokens/thread),
// blocks [bblocks, bblocks+rblocks) do table repack (1 row/thread).
__global__ __launch_bounds__(256) void k_prep(const int*   __restrict__ vox,
                                              const float* __restrict__ table,
                                              int T, int n_voxels,
                                              int rows, int bblocks) {
    if (blockIdx.x < (unsigned)bblocks) {
        // ---- bounds part ----
        int i = blockIdx.x * 256 + threadIdx.x;
        int base = i * 4;
        if (base >= T) return;

        int4 q = __ldg((const int4*)vox + i);
        int vals[5];
        vals[0] = q.x; vals[1] = q.y; vals[2] = q.z; vals[3] = q.w;
        vals[4] = (base + 4 >= T) ? -1 : __ldg(vox + base + 4);

        if (base == 0) {
            for (int w = 0; w < vals[0]; w++) { g_start[w] = 0; g_end[w] = 0; }
            g_start[vals[0]] = 0;
        }
#pragma unroll
        for (int j = 0; j < 4; j++) {
            int idx = base + j;
            int cur = vals[j];
            if (idx == T - 1) {
                g_end[cur] = T;
                for (int w = cur + 1; w < n_voxels; w++) { g_start[w] = T; g_end[w] = T; }
            } else {
                int nx = vals[j + 1];
                if (nx != cur) {
                    g_end[cur]  = idx + 1;
                    g_start[nx] = idx + 1;
                    for (int w = cur + 1; w < nx; w++) { g_start[w] = idx + 1; g_end[w] = idx + 1; }
                }
            }
        }
    } else {
        // ---- repack part ----
        int r = (blockIdx.x - bblocks) * 256 + threadIdx.x;
        if (r >= rows) return;
        const float4* src = (const float4*)(table + (size_t)r * D);
        float4 a = __ldg(src + 0);
        float4 b = __ldg(src + 1);
        float4 c = __ldg(src + 2);
        __half2 h[8];
        h[0] = __floats2half2_rn(a.x, a.y);
        h[1] = __floats2half2_rn(a.z, a.w);
        h[2] = __floats2half2_rn(b.x, b.y);
        h[3] = __floats2half2_rn(b.z, b.w);
        h[4] = __floats2half2_rn(c.x, c.y);
        h[5] = __floats2half2_rn(c.z, c.w);
        h[6] = __floats2half2_rn(0.f, 0.f);
        h[7] = __floats2half2_rn(0.f, 0.f);
        uint4* dst = (uint4*)(g_tab + (size_t)r * ROW_PAD);
        dst[0] = *(uint4*)&h[0];
        dst[1] = *(uint4*)&h[4];
    }
}

__device__ __forceinline__ void acc_row(float* acc, uint4 p0, uint4 p1) {
    float2 f;
    f = __half22float2(*(const __half2*)&p0.x); acc[0]  += f.x; acc[1]  += f.y;
    f = __half22float2(*(const __half2*)&p0.y); acc[2]  += f.x; acc[3]  += f.y;
    f = __half22float2(*(const __half2*)&p0.z); acc[4]  += f.x; acc[5]  += f.y;
    f = __half22float2(*(const __half2*)&p0.w); acc[6]  += f.x; acc[7]  += f.y;
    f = __half22float2(*(const __half2*)&p1.x); acc[8]  += f.x; acc[9]  += f.y;
    f = __half22float2(*(const __half2*)&p1.y); acc[10] += f.x; acc[11] += f.y;
}

__global__ __launch_bounds__(256) void k_pool(const int* __restrict__ seg,
                                              float*     __restrict__ out,
                                              int n_voxels) {
    __shared__ int s_seg[CHUNK];

    int v  = blockIdx.x * 256 + threadIdx.x;
    int v0 = blockIdx.x * 256;
    int vL = min(v0 + 255, n_voxels - 1);

    int rs = g_start[v0];
    int re = g_end[vL];

    int s, e;
    if (v < n_voxels) { s = g_start[v]; e = g_end[v]; }
    else              { s = rs;         e = rs;       }

    float acc[D];
#pragma unroll
    for (int d = 0; d < D; d++) acc[d] = 0.0f;

    for (int cbase = rs; cbase < re; cbase += CHUNK) {
        int clim = min(re, cbase + CHUNK);
        __syncthreads();
        for (int j = cbase + threadIdx.x; j < clim; j += 256)
            s_seg[j - cbase] = __ldg(seg + j);
        __syncthreads();

        int t0 = max(s, cbase);
        int t1 = min(e, clim);
        int t  = t0;

        // unroll-by-2: batch 4 independent 16B gathers before accumulating
        for (; t + 1 < t1; t += 2) {
            int sg0 = s_seg[t - cbase];
            int sg1 = s_seg[t + 1 - cbase];
            const uint4* r0 = (const uint4*)(g_tab + (size_t)sg0 * ROW_PAD);
            const uint4* r1 = (const uint4*)(g_tab + (size_t)sg1 * ROW_PAD);
            uint4 a0 = __ldg(r0 + 0);
            uint4 a1 = __ldg(r0 + 1);
            uint4 b0 = __ldg(r1 + 0);
            uint4 b1 = __ldg(r1 + 1);
            acc_row(acc, a0, a1);
            acc_row(acc, b0, b1);
        }
        if (t < t1) {
            int sg = s_seg[t - cbase];
            const uint4* r0 = (const uint4*)(g_tab + (size_t)sg * ROW_PAD);
            uint4 a0 = __ldg(r0 + 0);
            uint4 a1 = __ldg(r0 + 1);
            acc_row(acc, a0, a1);
        }
    }

    if (v >= n_voxels) return;

    int cnt = e - s;
    float invc = 1.0f / (float)(cnt > 0 ? cnt : 1);

    float m[D];
    float norm2 = 0.0f;
#pragma unroll
    for (int d = 0; d < D; d++) {
        m[d] = acc[d] * invc;
        norm2 += m[d] * m[d];
    }
    float norm = sqrtf(norm2);
    float inv  = 1.0f / fmaxf(norm, EPS);

    float4 o0 = make_float4(m[0] * inv, m[1] * inv, m[2]  * inv, m[3]  * inv);
    float4 o1 = make_float4(m[4] * inv, m[5] * inv, m[6]  * inv, m[7]  * inv);
    float4 o2 = make_float4(m[8] * inv, m[9] * inv, m[10] * inv, m[11] * inv);

    float4* orow = (float4*)(out + (size_t)v * D);
    orow[0] = o0;
    orow[1] = o1;
    orow[2] = o2;
}

extern "C" void kernel_launch(void* const* d_in, const int* in_sizes, int n_in,
                              void* d_out, int out_size) {
    const float* table = (const float*)d_in[0];
    const int*   seg   = (const int*)  d_in[1];
    const int*   vox   = (const int*)  d_in[2];
    float*       out   = (float*)      d_out;

    int rows     = in_sizes[0] / D;
    int T        = in_sizes[1];
    int n_voxels = out_size / D;

    int bblocks = (T / 4 + 255) / 256;
    int rblocks = (rows + 255) / 256;
    k_prep<<<bblocks + rblocks, 256>>>(vox, table, T, n_voxels, rows, bblocks);
    k_pool<<<(n_voxels + 255) / 256, 256>>>(seg, out, n_voxels);
}

// round 6
// speedup vs baseline: 1.3239x; 1.1356x over previous
#include <cuda_runtime.h>
#include <cuda_fp16.h>
#include <math.h>

#define NV_MAX   1048576
#define MAX_SEG  50000
#define D        12
#define ROW_PAD  16          // halves per padded row = 32 bytes = 1 L2 sector
#define EPS      1e-12f
#define CHUNK    2048        // seg-id staging tile (8KB smem)
#define VPB      128         // voxels per block (2 lanes per voxel)

__device__ int g_start[NV_MAX];
__device__ int g_end[NV_MAX];
__device__ __align__(32) __half g_tab[MAX_SEG * ROW_PAD];

// Fused prep: blocks [0, bblocks) find run boundaries (4 tokens/thread, with
// gap-fill so bounds are monotone); remaining blocks repack the table to fp16.
__global__ __launch_bounds__(256) void k_prep(const int*   __restrict__ vox,
                                              const float* __restrict__ table,
                                              int T, int n_voxels,
                                              int rows, int bblocks) {
    if (blockIdx.x < (unsigned)bblocks) {
        int i = blockIdx.x * 256 + threadIdx.x;
        int base = i * 4;
        if (base >= T) return;

        int4 q = __ldg((const int4*)vox + i);
        int vals[5];
        vals[0] = q.x; vals[1] = q.y; vals[2] = q.z; vals[3] = q.w;
        vals[4] = (base + 4 >= T) ? -1 : __ldg(vox + base + 4);

        if (base == 0) {
            for (int w = 0; w < vals[0]; w++) { g_start[w] = 0; g_end[w] = 0; }
            g_start[vals[0]] = 0;
        }
#pragma unroll
        for (int j = 0; j < 4; j++) {
            int idx = base + j;
            int cur = vals[j];
            if (idx == T - 1) {
                g_end[cur] = T;
                for (int w = cur + 1; w < n_voxels; w++) { g_start[w] = T; g_end[w] = T; }
            } else {
                int nx = vals[j + 1];
                if (nx != cur) {
                    g_end[cur]  = idx + 1;
                    g_start[nx] = idx + 1;
                    for (int w = cur + 1; w < nx; w++) { g_start[w] = idx + 1; g_end[w] = idx + 1; }
                }
            }
        }
    } else {
        int r = (blockIdx.x - bblocks) * 256 + threadIdx.x;
        if (r >= rows) return;
        const float4* src = (const float4*)(table + (size_t)r * D);
        float4 a = __ldg(src + 0);
        float4 b = __ldg(src + 1);
        float4 c = __ldg(src + 2);
        __half2 h[8];
        h[0] = __floats2half2_rn(a.x, a.y);
        h[1] = __floats2half2_rn(a.z, a.w);
        h[2] = __floats2half2_rn(b.x, b.y);
        h[3] = __floats2half2_rn(b.z, b.w);
        h[4] = __floats2half2_rn(c.x, c.y);
        h[5] = __floats2half2_rn(c.z, c.w);
        h[6] = __floats2half2_rn(0.f, 0.f);
        h[7] = __floats2half2_rn(0.f, 0.f);
        uint4* dst = (uint4*)(g_tab + (size_t)r * ROW_PAD);
        dst[0] = *(uint4*)&h[0];
        dst[1] = *(uint4*)&h[4];
    }
}

// Pair-cooperative pool: lanes (2k, 2k+1) share voxel k. Even lane loads/owns
// dims 0-7, odd lane loads/owns dims 8-11. One LDG.128 per lane per token ->
// paired lanes hit the same 128B line -> 1 L1 wavefront per token (was 2).
__global__ __launch_bounds__(256) void k_pool(const int* __restrict__ seg,
                                              float*     __restrict__ out,
                                              int n_voxels) {
    __shared__ int s_seg[CHUNK];

    int tid = threadIdx.x;
    int p   = tid & 1;                       // parity within pair
    int v   = blockIdx.x * VPB + (tid >> 1); // voxel for this pair
    int v0  = blockIdx.x * VPB;
    int vL  = min(v0 + VPB - 1, n_voxels - 1);

    int rs = g_start[v0];
    int re = g_end[vL];

    int s, e;
    if (v < n_voxels) { s = g_start[v]; e = g_end[v]; }
    else              { s = rs;         e = rs;       }

    // even lane: 8 accumulators (dims 0-7); odd: 4 used (dims 8-11)
    float acc[8];
#pragma unroll
    for (int d = 0; d < 8; d++) acc[d] = 0.0f;

    for (int cbase = rs; cbase < re; cbase += CHUNK) {
        int clim = min(re, cbase + CHUNK);
        __syncthreads();
        for (int j = cbase + tid; j < clim; j += 256)
            s_seg[j - cbase] = __ldg(seg + j);
        __syncthreads();

        int t0 = max(s, cbase);
        int t1 = min(e, clim);
        int t  = t0;

        for (; t + 1 < t1; t += 2) {
            int sg0 = s_seg[t - cbase];
            int sg1 = s_seg[t + 1 - cbase];
            uint4 q0 = __ldg((const uint4*)(g_tab + (size_t)sg0 * ROW_PAD) + p);
            uint4 q1 = __ldg((const uint4*)(g_tab + (size_t)sg1 * ROW_PAD) + p);
            float2 f;
            f = __half22float2(*(const __half2*)&q0.x); acc[0] += f.x; acc[1] += f.y;
            f = __half22float2(*(const __half2*)&q0.y); acc[2] += f.x; acc[3] += f.y;
            f = __half22float2(*(const __half2*)&q0.z); acc[4] += f.x; acc[5] += f.y;
            f = __half22float2(*(const __half2*)&q0.w); acc[6] += f.x; acc[7] += f.y;
            f = __half22float2(*(const __half2*)&q1.x); acc[0] += f.x; acc[1] += f.y;
            f = __half22float2(*(const __half2*)&q1.y); acc[2] += f.x; acc[3] += f.y;
            f = __half22float2(*(const __half2*)&q1.z); acc[4] += f.x; acc[5] += f.y;
            f = __half22float2(*(const __half2*)&q1.w); acc[6] += f.x; acc[7] += f.y;
        }
        if (t < t1) {
            int sg = s_seg[t - cbase];
            uint4 q0 = __ldg((const uint4*)(g_tab + (size_t)sg * ROW_PAD) + p);
            float2 f;
            f = __half22float2(*(const __half2*)&q0.x); acc[0] += f.x; acc[1] += f.y;
            f = __half22float2(*(const __half2*)&q0.y); acc[2] += f.x; acc[3] += f.y;
            f = __half22float2(*(const __half2*)&q0.z); acc[4] += f.x; acc[5] += f.y;
            f = __half22float2(*(const __half2*)&q0.w); acc[6] += f.x; acc[7] += f.y;
        }
    }

    // Epilogue: even lane owns m[0..7], odd lane owns m[8..11] (in acc[0..3];
    // odd's acc[4..7] accumulated pad zeros, harmless).
    int cnt = e - s;
    float invc = 1.0f / (float)(cnt > 0 ? cnt : 1);

    float m[8];
    float n2p = 0.0f;
    int nd = p ? 4 : 8;
#pragma unroll
    for (int d = 0; d < 8; d++) {
        m[d] = acc[d] * invc;
        if (d < nd) n2p += m[d] * m[d];
    }
    float norm2 = n2p + __shfl_xor_sync(0xFFFFFFFFu, n2p, 1);
    float inv   = 1.0f / fmaxf(sqrtf(norm2), EPS);

    if (v < n_voxels) {
        float4* orow = (float4*)(out + (size_t)v * D);
        if (p == 0) {
            orow[0] = make_float4(m[0] * inv, m[1] * inv, m[2] * inv, m[3] * inv);
            orow[1] = make_float4(m[4] * inv, m[5] * inv, m[6] * inv, m[7] * inv);
        } else {
            orow[2] = make_float4(m[0] * inv, m[1] * inv, m[2] * inv, m[3] * inv);
        }
    }
}

extern "C" void kernel_launch(void* const* d_in, const int* in_sizes, int n_in,
                              void* d_out, int out_size) {
    const float* table = (const float*)d_in[0];
    const int*   seg   = (const int*)  d_in[1];
    const int*   vox   = (const int*)  d_in[2];
    float*       out   = (float*)      d_out;

    int rows     = in_sizes[0] / D;
    int T        = in_sizes[1];
    int n_voxels = out_size / D;

    int bblocks = (T / 4 + 255) / 256;
    int rblocks = (rows + 255) / 256;
    k_prep<<<bblocks + rblocks, 256>>>(vox, table, T, n_voxels, rows, bblocks);
    k_pool<<<(n_voxels + VPB - 1) / VPB, 256>>>(seg, out, n_voxels);
}

// round 7
// speedup vs baseline: 1.3996x; 1.0571x over previous
#include <cuda_runtime.h>
#include <cuda_fp16.h>
#include <math.h>

#define NV_MAX   1048576
#define MAX_SEG  50000
#define D        12
#define ROW_PAD  16          // halves per padded row = 32 bytes = 1 L2 sector
#define EPS      1e-12f
#define CHUNK    2048        // seg-id staging tile (8KB smem)
#define VPB      128         // voxels per block (2 lanes per voxel)

__device__ int g_start[NV_MAX];
__device__ int g_end[NV_MAX];
__device__ __align__(32) __half g_tab[MAX_SEG * ROW_PAD];

// Fused prep: blocks [0, bblocks) find run boundaries (4 tokens/thread, with
// gap-fill so bounds are monotone); remaining blocks repack the table to fp16.
__global__ __launch_bounds__(256) void k_prep(const int*   __restrict__ vox,
                                              const float* __restrict__ table,
                                              int T, int n_voxels,
                                              int rows, int bblocks) {
    if (blockIdx.x < (unsigned)bblocks) {
        int i = blockIdx.x * 256 + threadIdx.x;
        int base = i * 4;
        if (base >= T) return;

        int4 q = __ldg((const int4*)vox + i);
        int vals[5];
        vals[0] = q.x; vals[1] = q.y; vals[2] = q.z; vals[3] = q.w;
        vals[4] = (base + 4 >= T) ? -1 : __ldg(vox + base + 4);

        if (base == 0) {
            for (int w = 0; w < vals[0]; w++) { g_start[w] = 0; g_end[w] = 0; }
            g_start[vals[0]] = 0;
        }
#pragma unroll
        for (int j = 0; j < 4; j++) {
            int idx = base + j;
            int cur = vals[j];
            if (idx == T - 1) {
                g_end[cur] = T;
                for (int w = cur + 1; w < n_voxels; w++) { g_start[w] = T; g_end[w] = T; }
            } else {
                int nx = vals[j + 1];
                if (nx != cur) {
                    g_end[cur]  = idx + 1;
                    g_start[nx] = idx + 1;
                    for (int w = cur + 1; w < nx; w++) { g_start[w] = idx + 1; g_end[w] = idx + 1; }
                }
            }
        }
    } else {
        int r = (blockIdx.x - bblocks) * 256 + threadIdx.x;
        if (r >= rows) return;
        const float4* src = (const float4*)(table + (size_t)r * D);
        float4 a = __ldg(src + 0);
        float4 b = __ldg(src + 1);
        float4 c = __ldg(src + 2);
        __half2 h[8];
        h[0] = __floats2half2_rn(a.x, a.y);
        h[1] = __floats2half2_rn(a.z, a.w);
        h[2] = __floats2half2_rn(b.x, b.y);
        h[3] = __floats2half2_rn(b.z, b.w);
        h[4] = __floats2half2_rn(c.x, c.y);
        h[5] = __floats2half2_rn(c.z, c.w);
        h[6] = __floats2half2_rn(0.f, 0.f);
        h[7] = __floats2half2_rn(0.f, 0.f);
        uint4* dst = (uint4*)(g_tab + (size_t)r * ROW_PAD);
        dst[0] = *(uint4*)&h[0];
        dst[1] = *(uint4*)&h[4];
    }
}

#define H2(u) (*(const __half2*)&(u))

__device__ __forceinline__ void acc_half4(float* acc, __half2 a, __half2 b,
                                          __half2 c, __half2 d) {
    float2 f;
    f = __half22float2(a); acc[0] += f.x; acc[1] += f.y;
    f = __half22float2(b); acc[2] += f.x; acc[3] += f.y;
    f = __half22float2(c); acc[4] += f.x; acc[5] += f.y;
    f = __half22float2(d); acc[6] += f.x; acc[7] += f.y;
}

// Pair-cooperative pool: lanes (2k, 2k+1) share voxel k; even lane handles
// dims 0-7, odd lane dims 8-11(+pad). One 16B LDG per lane per token; paired
// lanes hit the same 128B line -> 1 L1 wavefront per token.
__global__ __launch_bounds__(256) void k_pool(const int* __restrict__ seg,
                                              float*     __restrict__ out,
                                              int n_voxels) {
    __shared__ int s_seg[CHUNK];

    int tid = threadIdx.x;
    int p   = tid & 1;
    int v   = blockIdx.x * VPB + (tid >> 1);
    int v0  = blockIdx.x * VPB;
    int vL  = min(v0 + VPB - 1, n_voxels - 1);

    int rs = g_start[v0];
    int re = g_end[vL];

    int s, e;
    if (v < n_voxels) { s = g_start[v]; e = g_end[v]; }
    else              { s = rs;         e = rs;       }

    float acc[8];
#pragma unroll
    for (int d = 0; d < 8; d++) acc[d] = 0.0f;

    for (int cbase = rs; cbase < re; cbase += CHUNK) {
        int clim = min(re, cbase + CHUNK);
        __syncthreads();
        for (int j = cbase + tid; j < clim; j += 256)
            s_seg[j - cbase] = __ldg(seg + j);
        __syncthreads();

        int t0 = max(s, cbase);
        int t1 = min(e, clim);
        int t  = t0;

        // unroll-4: 4 loads in flight, fp16 pre-add of token pairs
        for (; t + 3 < t1; t += 4) {
            int i0 = t - cbase;
            int sg0 = s_seg[i0];
            int sg1 = s_seg[i0 + 1];
            int sg2 = s_seg[i0 + 2];
            int sg3 = s_seg[i0 + 3];
            uint4 q0 = __ldg((const uint4*)(g_tab + (size_t)sg0 * ROW_PAD) + p);
            uint4 q1 = __ldg((const uint4*)(g_tab + (size_t)sg1 * ROW_PAD) + p);
            uint4 q2 = __ldg((const uint4*)(g_tab + (size_t)sg2 * ROW_PAD) + p);
            uint4 q3 = __ldg((const uint4*)(g_tab + (size_t)sg3 * ROW_PAD) + p);

            __half2 a0 = __hadd2(H2(q0.x), H2(q1.x));
            __half2 a1 = __hadd2(H2(q0.y), H2(q1.y));
            __half2 a2 = __hadd2(H2(q0.z), H2(q1.z));
            __half2 a3 = __hadd2(H2(q0.w), H2(q1.w));
            __half2 b0 = __hadd2(H2(q2.x), H2(q3.x));
            __half2 b1 = __hadd2(H2(q2.y), H2(q3.y));
            __half2 b2 = __hadd2(H2(q2.z), H2(q3.z));
            __half2 b3 = __hadd2(H2(q2.w), H2(q3.w));

            acc_half4(acc, a0, a1, a2, a3);
            acc_half4(acc, b0, b1, b2, b3);
        }
        // tail: exact fp32 path
        for (; t < t1; t++) {
            int sg = s_seg[t - cbase];
            uint4 q = __ldg((const uint4*)(g_tab + (size_t)sg * ROW_PAD) + p);
            acc_half4(acc, H2(q.x), H2(q.y), H2(q.z), H2(q.w));
        }
    }

    int cnt = e - s;
    float invc = 1.0f / (float)(cnt > 0 ? cnt : 1);

    float m[8];
    float n2p = 0.0f;
    int nd = p ? 4 : 8;
#pragma unroll
    for (int d = 0; d < 8; d++) {
        m[d] = acc[d] * invc;
        if (d < nd) n2p += m[d] * m[d];
    }
    float norm2 = n2p + __shfl_xor_sync(0xFFFFFFFFu, n2p, 1);
    float inv   = 1.0f / fmaxf(sqrtf(norm2), EPS);

    if (v < n_voxels) {
        float4* orow = (float4*)(out + (size_t)v * D);
        if (p == 0) {
            orow[0] = make_float4(m[0] * inv, m[1] * inv, m[2] * inv, m[3] * inv);
            orow[1] = make_float4(m[4] * inv, m[5] * inv, m[6] * inv, m[7] * inv);
        } else {
            orow[2] = make_float4(m[0] * inv, m[1] * inv, m[2] * inv, m[3] * inv);
        }
    }
}

extern "C" void kernel_launch(void* const* d_in, const int* in_sizes, int n_in,
                              void* d_out, int out_size) {
    const float* table = (const float*)d_in[0];
    const int*   seg   = (const int*)  d_in[1];
    const int*   vox   = (const int*)  d_in[2];
    float*       out   = (float*)      d_out;

    int rows     = in_sizes[0] / D;
    int T        = in_sizes[1];
    int n_voxels = out_size / D;

    int bblocks = (T / 4 + 255) / 256;
    int rblocks = (rows + 255) / 256;
    k_prep<<<bblocks + rblocks, 256>>>(vox, table, T, n_voxels, rows, bblocks);
    k_pool<<<(n_voxels + VPB - 1) / VPB, 256>>>(seg, out, n_voxels);
}